// round 13
// baseline (speedup 1.0000x reference)
#include <cuda_runtime.h>
#include <cuda_bf16.h>
#include <cstdint>

#define NEGC -1000000000.0f
#define B_ 8
#define S_ 4096
#define D_ 256
#define KC 128
#define NSPLIT 8

// ---------------------------------------------------------------------------
// Scratch (__device__ globals; no allocation allowed)
// ---------------------------------------------------------------------------
__device__ __nv_bfloat16 g_Kc[B_ * S_ * D_];              // [b][s][d]  K * invb
__device__ __nv_bfloat16 g_Vc[B_ * S_ * D_];              // [b][s][e]  V
__device__ __nv_bfloat16 g_Qc[B_ * S_ * D_];              // [b][s][d]  Q/sumsq (masked=0)
__device__ __nv_bfloat16 g_s1part[NSPLIT * B_ * D_ * D_]; // per-split partials (bf16)
__device__ __nv_bfloat16 g_s1c[B_ * D_ * D_];             // [b][d][e]  bf16 (reduced)
__device__ float         g_tpart[B_ * 128 * D_];          // per-chunk colsum partials
__device__ unsigned char g_msk[B_ * S_];

// ---------------------------------------------------------------------------
// Helpers
// ---------------------------------------------------------------------------
__device__ __forceinline__ void cp16(void* smem_dst, const void* gsrc) {
    uint32_t a = (uint32_t)__cvta_generic_to_shared(smem_dst);
    asm volatile("cp.async.cg.shared.global [%0], [%1], 16;" :: "r"(a), "l"(gsrc));
}
__device__ __forceinline__ void cp_commit() { asm volatile("cp.async.commit_group;"); }
#define CP_WAIT(N) asm volatile("cp.async.wait_group %0;" :: "n"(N))

__device__ __forceinline__ void ldsmx4(uint32_t* r, uint32_t addr) {
    asm volatile("ldmatrix.sync.aligned.m8n8.x4.shared.b16 {%0,%1,%2,%3}, [%4];"
                 : "=r"(r[0]), "=r"(r[1]), "=r"(r[2]), "=r"(r[3]) : "r"(addr));
}
__device__ __forceinline__ void ldsmx4t(uint32_t* r, uint32_t addr) {
    asm volatile("ldmatrix.sync.aligned.m8n8.x4.trans.shared.b16 {%0,%1,%2,%3}, [%4];"
                 : "=r"(r[0]), "=r"(r[1]), "=r"(r[2]), "=r"(r[3]) : "r"(addr));
}
__device__ __forceinline__ void mma16816(float* d, const uint32_t* a, const uint32_t* b) {
    asm volatile(
        "mma.sync.aligned.m16n8k16.row.col.f32.bf16.bf16.f32 "
        "{%0,%1,%2,%3},{%4,%5,%6,%7},{%8,%9},{%0,%1,%2,%3};"
        : "+f"(d[0]), "+f"(d[1]), "+f"(d[2]), "+f"(d[3])
        : "r"(a[0]), "r"(a[1]), "r"(a[2]), "r"(a[3]), "r"(b[0]), "r"(b[1]));
}

__device__ __forceinline__ uint4 pack8(float4 a, float4 b, float m) {
    __nv_bfloat162 h0 = __floats2bfloat162_rn(a.x * m, a.y * m);
    __nv_bfloat162 h1 = __floats2bfloat162_rn(a.z * m, a.w * m);
    __nv_bfloat162 h2 = __floats2bfloat162_rn(b.x * m, b.y * m);
    __nv_bfloat162 h3 = __floats2bfloat162_rn(b.z * m, b.w * m);
    uint4 o;
    o.x = *reinterpret_cast<uint32_t*>(&h0);
    o.y = *reinterpret_cast<uint32_t*>(&h1);
    o.z = *reinterpret_cast<uint32_t*>(&h2);
    o.w = *reinterpret_cast<uint32_t*>(&h3);
    return o;
}

// ---------------------------------------------------------------------------
// prepKV: invb per row, Kc=bf16(K*invb), Vc=bf16(V),
// tpart[b][chunk][e] = sum_{s in chunk} (rowsum(K)*invb) * V[s,e]  (plain store).
// grid (S/32, B), 256 threads.
// ---------------------------------------------------------------------------
__global__ __launch_bounds__(256) void prepKV_kernel(const float* __restrict__ K,
                                                     const float* __restrict__ V) {
    __shared__ float Vsm[32][264];
    __shared__ float csm[32];
    const int b = blockIdx.y, s0 = blockIdx.x * 32;
    const int tid = threadIdx.x, wid = tid >> 5, lane = tid & 31;
    const size_t base = ((size_t)b * S_ + s0) * D_;

#pragma unroll
    for (int i = 0; i < 4; i++) {
        int r = wid * 4 + i;
        const float4* kr = reinterpret_cast<const float4*>(K + base + (size_t)r * D_) + lane * 2;
        float4 k0 = kr[0], k1 = kr[1];
        float sk = k0.x * k0.x + k0.y * k0.y + k0.z * k0.z + k0.w * k0.w
                 + k1.x * k1.x + k1.y * k1.y + k1.z * k1.z + k1.w * k1.w;
        float rk = k0.x + k0.y + k0.z + k0.w + k1.x + k1.y + k1.z + k1.w;
#pragma unroll
        for (int o = 16; o; o >>= 1) {
            sk += __shfl_xor_sync(0xFFFFFFFFu, sk, o);
            rk += __shfl_xor_sync(0xFFFFFFFFu, rk, o);
        }
        float ib = 1.0f / sk;
        reinterpret_cast<uint4*>(g_Kc)[(base + (size_t)r * D_) / 8 + lane] = pack8(k0, k1, ib);

        const float4* vr = reinterpret_cast<const float4*>(V + base + (size_t)r * D_) + lane * 2;
        float4 v0 = vr[0], v1 = vr[1];
        *reinterpret_cast<float4*>(&Vsm[r][lane * 8])     = v0;
        *reinterpret_cast<float4*>(&Vsm[r][lane * 8 + 4]) = v1;
        reinterpret_cast<uint4*>(g_Vc)[(base + (size_t)r * D_) / 8 + lane] = pack8(v0, v1, 1.0f);
        if (lane == 0) csm[r] = rk * ib;
    }
    __syncthreads();

    float acc = 0.f;
    int e = tid;
#pragma unroll 8
    for (int s = 0; s < 32; s++) acc += csm[s] * Vsm[s][e];
    g_tpart[(b * 128 + blockIdx.x) * D_ + e] = acc;   // plain store, no zeroing needed
}

// ---------------------------------------------------------------------------
// prepQ: inline mask-dtype detect (first 8KB scan), Qc = bf16(Q/sumsq),
// masked rows -> 0; mask byte out.  grid (S/32, B), 256 threads.
// ---------------------------------------------------------------------------
__global__ __launch_bounds__(256) void prepQ_kernel(const float* __restrict__ Q,
                                                    const void* __restrict__ m) {
    const int b = blockIdx.y, s0 = blockIdx.x * 32;
    const int tid = threadIdx.x, wid = tid >> 5, lane = tid & 31;
    const size_t base = ((size_t)b * S_ + s0) * D_;

    // Detect dtype from the first 8192 bytes (2048 words; safe for all dtypes).
    const unsigned int* mw = reinterpret_cast<const unsigned int*>(m);
    int big = 0, odd = 0;
#pragma unroll
    for (int it = 0; it < 8; it++) {
        unsigned int w = mw[tid + it * 256];
        unsigned int b0 = w & 0xFFu, b1 = (w >> 8) & 0xFFu,
                     b2 = (w >> 16) & 0xFFu, b3 = w >> 24;
        if (b0 > 1u || b1 > 1u || b2 > 1u || b3 > 1u) big = 1;
        if (w != 0u && w != 1u) odd = 1;
    }
    int anybig = __syncthreads_or(big);
    int anyodd = __syncthreads_or(odd);
    const int mode = anybig ? 2 : (anyodd ? 0 : 1);

#pragma unroll
    for (int i = 0; i < 4; i++) {
        int r = wid * 4 + i;
        int g = b * S_ + s0 + r;
        const float4* qr = reinterpret_cast<const float4*>(Q + base + (size_t)r * D_) + lane * 2;
        float4 q0 = qr[0], q1 = qr[1];
        float sq = q0.x * q0.x + q0.y * q0.y + q0.z * q0.z + q0.w * q0.w
                 + q1.x * q1.x + q1.y * q1.y + q1.z * q1.z + q1.w * q1.w;
#pragma unroll
        for (int o = 16; o; o >>= 1) sq += __shfl_xor_sync(0xFFFFFFFFu, sq, o);
        bool mk;
        if (mode == 2)      mk = (reinterpret_cast<const float*>(m)[g] != 0.0f);
        else if (mode == 1) mk = (reinterpret_cast<const int*>(m)[g] != 0);
        else                mk = (reinterpret_cast<const unsigned char*>(m)[g] != 0);
        float mul = mk ? 0.0f : 1.0f / sq;
        reinterpret_cast<uint4*>(g_Qc)[(base + (size_t)r * D_) / 8 + lane] = pack8(q0, q1, mul);
        if (lane == 0) g_msk[g] = mk ? 1 : 0;
    }
}

// ---------------------------------------------------------------------------
// GEMM1: CTA tile 256(d) x 128(e).  8 warps (4m x 2n), warp tile 64x64.
// A = Kc[s][d] (trans ldmatrix); B = Vc[s][e].  Partials bf16.
// grid (2 et, NSPLIT, B).  2-stage cp.async, KC=128.
// ---------------------------------------------------------------------------
#define SRA1 264
#define SRB  136
#define A1BUF (KC * SRA1)
#define B1BUF (KC * SRB)
#define STG1  (A1BUF + B1BUF)
#define G1_SMEM (2 * STG1 * (int)sizeof(__nv_bfloat16))   // 204800 B

__global__ __launch_bounds__(256) void gemm1_kernel() {
    extern __shared__ __nv_bfloat16 dsm[];

    const int tid = threadIdx.x, wid = tid >> 5, lane = tid & 31;
    const int b = blockIdx.z;
    const int et = blockIdx.x * 128;
    const int s0 = blockIdx.y * (S_ / NSPLIT);
    const int m0 = (wid >> 1) * 64, n0 = (wid & 1) * 64;
    const __nv_bfloat16* Kb = g_Kc + (size_t)b * S_ * D_;
    const __nv_bfloat16* Vb = g_Vc + (size_t)b * S_ * D_;

    float acc[4][8][4];
#pragma unroll
    for (int i = 0; i < 4; i++)
#pragma unroll
        for (int j = 0; j < 8; j++)
#pragma unroll
            for (int q = 0; q < 4; q++) acc[i][j][q] = 0.f;

    const int r8 = lane & 7, sel = lane >> 3;
    const int atr = (sel >> 1) * 8 + r8, atc = (sel & 1) * 8;
    const int btr = (sel & 1) * 8 + r8, btc = (sel >> 1) * 8;

    auto load = [&](int ch, int st) {
        const int ss = s0 + ch * KC;
        __nv_bfloat16* Ab = dsm + st * STG1;
        __nv_bfloat16* Bb = Ab + A1BUF;
#pragma unroll
        for (int it = 0; it < 16; it++) {
            int ci = tid + it * 256;
            int row = ci >> 5, c16 = ci & 31;
            cp16(Ab + row * SRA1 + c16 * 8, Kb + (size_t)(ss + row) * D_ + c16 * 8);
        }
#pragma unroll
        for (int it = 0; it < 8; it++) {
            int ci = tid + it * 256;
            int row = ci >> 4, c16 = ci & 15;
            cp16(Bb + row * SRB + c16 * 8, Vb + (size_t)(ss + row) * D_ + et + c16 * 8);
        }
    };

    const int NCH = (S_ / NSPLIT) / KC;   // 4
    load(0, 0); cp_commit();
    for (int ch = 0; ch < NCH; ch++) {
        if (ch + 1 < NCH) { load(ch + 1, (ch + 1) & 1); cp_commit(); CP_WAIT(1); }
        else CP_WAIT(0);
        __syncthreads();
        uint32_t Aaddr = (uint32_t)__cvta_generic_to_shared(dsm + (ch & 1) * STG1);
        uint32_t Baddr = Aaddr + A1BUF * 2;
#pragma unroll
        for (int kk = 0; kk < KC / 16; kk++) {
            uint32_t af[4][4], bf[4][4];
#pragma unroll
            for (int mt = 0; mt < 4; mt++)
                ldsmx4(af[mt], Aaddr + ((kk * 16 + atr) * SRA1 + m0 + mt * 16 + atc) * 2);
#pragma unroll
            for (int nt = 0; nt < 4; nt++)
                ldsmx4t(bf[nt], Baddr + ((kk * 16 + btr) * SRB + n0 + nt * 16 + btc) * 2);
#pragma unroll
            for (int mt = 0; mt < 4; mt++)
#pragma unroll
                for (int nt = 0; nt < 4; nt++) {
                    mma16816(acc[mt][nt * 2],     af[mt], &bf[nt][0]);
                    mma16816(acc[mt][nt * 2 + 1], af[mt], &bf[nt][2]);
                }
        }
        __syncthreads();
    }

    __nv_bfloat16* s1p = g_s1part + ((size_t)blockIdx.y * B_ + b) * D_ * D_;
    const int tr = lane >> 2, tc = (lane & 3) * 2;
#pragma unroll
    for (int mt = 0; mt < 4; mt++) {
        int gd0 = m0 + mt * 16 + tr;
#pragma unroll
        for (int nt = 0; nt < 8; nt++) {
            int ge = et + n0 + nt * 8 + tc;
            __nv_bfloat162 lo = __floats2bfloat162_rn(acc[mt][nt][0], acc[mt][nt][1]);
            __nv_bfloat162 hi = __floats2bfloat162_rn(acc[mt][nt][2], acc[mt][nt][3]);
            *reinterpret_cast<uint32_t*>(&s1p[(size_t)gd0 * D_ + ge]) =
                *reinterpret_cast<uint32_t*>(&lo);
            *reinterpret_cast<uint32_t*>(&s1p[(size_t)(gd0 + 8) * D_ + ge]) =
                *reinterpret_cast<uint32_t*>(&hi);
        }
    }
}

// Reduce NSPLIT bf16 partials (fp32 accumulate) -> bf16.  1 uint2 / thread.
__global__ __launch_bounds__(256) void s1conv_kernel() {
    const int i = blockIdx.x * 256 + threadIdx.x;   // uint2 index, B*D*D/4 total
    const int stride = (B_ * D_ * D_) / 4;
    float s0 = 0.f, s1 = 0.f, s2 = 0.f, s3 = 0.f;
#pragma unroll
    for (int sp = 0; sp < NSPLIT; sp++) {
        uint2 p = reinterpret_cast<const uint2*>(g_s1part)[sp * stride + i];
        float2 f0 = __bfloat1622float2(*reinterpret_cast<__nv_bfloat162*>(&p.x));
        float2 f1 = __bfloat1622float2(*reinterpret_cast<__nv_bfloat162*>(&p.y));
        s0 += f0.x; s1 += f0.y; s2 += f1.x; s3 += f1.y;
    }
    __nv_bfloat162 h0 = __floats2bfloat162_rn(s0, s1);
    __nv_bfloat162 h1 = __floats2bfloat162_rn(s2, s3);
    uint2 o;
    o.x = *reinterpret_cast<uint32_t*>(&h0);
    o.y = *reinterpret_cast<uint32_t*>(&h1);
    reinterpret_cast<uint2*>(g_s1c)[i] = o;
}

// ---------------------------------------------------------------------------
// GEMM2: CTA tile 256(s) x 128(e). 8 warps (4m x 2n), warp 64x64.
// A = Qc[s][d], B = s1c[d][e] (trans).  Prologue reduces g_tpart -> ts.
// Masked rows -> NEG/256 * ts[e] (exact).  grid (2 et, 16 st, B).
// ---------------------------------------------------------------------------
#define SRA2 136
#define A2BUF (256 * SRA2)
#define B2BUF (KC * SRB)
#define STG2  (A2BUF + B2BUF)
#define G2_SMEM (2 * STG2 * (int)sizeof(__nv_bfloat16))   // 208896 B

__global__ __launch_bounds__(256) void gemm2_kernel(float* __restrict__ out) {
    extern __shared__ __nv_bfloat16 dsm[];
    __shared__ float ts[128];

    const int tid = threadIdx.x, wid = tid >> 5, lane = tid & 31;
    const int b = blockIdx.z;
    const int et = blockIdx.x * 128, st = blockIdx.y * 256;
    const int m0 = (wid >> 1) * 64, n0 = (wid & 1) * 64;
    const __nv_bfloat16* Qb = g_Qc + ((size_t)b * S_ + st) * D_;
    const __nv_bfloat16* Sb = g_s1c + (size_t)b * D_ * D_;

    float acc[4][8][4];
#pragma unroll
    for (int i = 0; i < 4; i++)
#pragma unroll
        for (int j = 0; j < 8; j++)
#pragma unroll
            for (int q = 0; q < 4; q++) acc[i][j][q] = 0.f;

    const int r8 = lane & 7, sel = lane >> 3;
    const int anr = lane & 15, anc = (lane >> 4) * 8;
    const int btr = (sel & 1) * 8 + r8, btc = (sel >> 1) * 8;

    auto load = [&](int ch, int st_) {
        __nv_bfloat16* Ab = dsm + st_ * STG2;
        __nv_bfloat16* Bb = Ab + A2BUF;
#pragma unroll
        for (int it = 0; it < 16; it++) {
            int ci = tid + it * 256;
            int row = ci >> 4, c16 = ci & 15;
            cp16(Ab + row * SRA2 + c16 * 8, Qb + (size_t)row * D_ + ch * KC + c16 * 8);
        }
#pragma unroll
        for (int it = 0; it < 8; it++) {
            int ci = tid + it * 256;
            int row = ci >> 4, c16 = ci & 15;
            cp16(Bb + row * SRB + c16 * 8, Sb + (size_t)(ch * KC + row) * D_ + et + c16 * 8);
        }
    };

    load(0, 0); cp_commit();

    // Reduce t partials while the first cp.async stage is in flight.
    if (tid < 128) {
        const float* tp = g_tpart + (size_t)b * 128 * D_ + et + tid;
        float s = 0.f;
#pragma unroll 8
        for (int c = 0; c < 128; c++) s += tp[(size_t)c * D_];
        ts[tid] = s;
    }

    const int NCH = D_ / KC;   // 2
    for (int ch = 0; ch < NCH; ch++) {
        if (ch + 1 < NCH) { load(ch + 1, (ch + 1) & 1); cp_commit(); CP_WAIT(1); }
        else CP_WAIT(0);
        __syncthreads();
        uint32_t Aaddr = (uint32_t)__cvta_generic_to_shared(dsm + (ch & 1) * STG2);
        uint32_t Baddr = Aaddr + A2BUF * 2;
#pragma unroll
        for (int kk = 0; kk < KC / 16; kk++) {
            uint32_t af[4][4], bf[4][4];
#pragma unroll
            for (int mt = 0; mt < 4; mt++)
                ldsmx4(af[mt], Aaddr + ((m0 + mt * 16 + anr) * SRA2 + kk * 16 + anc) * 2);
#pragma unroll
            for (int nt = 0; nt < 4; nt++)
                ldsmx4t(bf[nt], Baddr + ((kk * 16 + btr) * SRB + n0 + nt * 16 + btc) * 2);
#pragma unroll
            for (int mt = 0; mt < 4; mt++)
#pragma unroll
                for (int nt = 0; nt < 4; nt++) {
                    mma16816(acc[mt][nt * 2],     af[mt], &bf[nt][0]);
                    mma16816(acc[mt][nt * 2 + 1], af[mt], &bf[nt][2]);
                }
        }
        __syncthreads();
    }

    const float inv_d = 1.0f / 256.0f;
    const float mc = NEGC * inv_d;
    float* ob = out + (size_t)b * S_ * D_;
    const int tr = lane >> 2, tc = (lane & 3) * 2;
#pragma unroll
    for (int mt = 0; mt < 4; mt++) {
        int r0l = m0 + mt * 16 + tr;
        int gs0 = st + r0l, gs1 = gs0 + 8;
        bool mk0 = (g_msk[b * S_ + gs0] != 0);
        bool mk1 = (g_msk[b * S_ + gs1] != 0);
#pragma unroll
        for (int nt = 0; nt < 8; nt++) {
            int gel = n0 + nt * 8 + tc;
            int ge = et + gel;
            float2 v0, v1;
            if (mk0) v0 = make_float2(mc * ts[gel], mc * ts[gel + 1]);
            else     v0 = make_float2(acc[mt][nt][0] * inv_d, acc[mt][nt][1] * inv_d);
            if (mk1) v1 = make_float2(mc * ts[gel], mc * ts[gel + 1]);
            else     v1 = make_float2(acc[mt][nt][2] * inv_d, acc[mt][nt][3] * inv_d);
            *reinterpret_cast<float2*>(&ob[(size_t)gs0 * D_ + ge]) = v0;
            *reinterpret_cast<float2*>(&ob[(size_t)gs1 * D_ + ge]) = v1;
        }
    }
}

// ---------------------------------------------------------------------------
extern "C" void kernel_launch(void* const* d_in, const int* in_sizes, int n_in,
                              void* d_out, int out_size) {
    const float* Q = reinterpret_cast<const float*>(d_in[0]);
    const float* K = reinterpret_cast<const float*>(d_in[1]);
    const float* V = reinterpret_cast<const float*>(d_in[2]);
    const void*  M = d_in[3];
    float* out = reinterpret_cast<float*>(d_out);

    cudaFuncSetAttribute(gemm1_kernel, cudaFuncAttributeMaxDynamicSharedMemorySize, G1_SMEM);
    cudaFuncSetAttribute(gemm2_kernel, cudaFuncAttributeMaxDynamicSharedMemorySize, G2_SMEM);

    {
        dim3 g(S_ / 32, B_);
        prepKV_kernel<<<g, 256>>>(K, V);
        prepQ_kernel<<<g, 256>>>(Q, M);
    }
    {
        dim3 g(2, NSPLIT, B_);
        gemm1_kernel<<<g, 256, G1_SMEM>>>();
    }
    s1conv_kernel<<<(B_ * D_ * D_) / (4 * 256), 256>>>();
    {
        dim3 g(2, S_ / 256, B_);
        gemm2_kernel<<<g, 256, G2_SMEM>>>(out);
    }
}

// round 14
// speedup vs baseline: 1.2217x; 1.2217x over previous
#include <cuda_runtime.h>
#include <cuda_bf16.h>
#include <cstdint>

#define NEGC -1000000000.0f
#define B_ 8
#define S_ 4096
#define D_ 256
#define KC 128
#define NSPLIT 8

// ---------------------------------------------------------------------------
// Scratch (__device__ globals; no allocation allowed)
// ---------------------------------------------------------------------------
__device__ __nv_bfloat16 g_Kc[B_ * S_ * D_];              // [b][s][d]  K * invb
__device__ __nv_bfloat16 g_Vc[B_ * S_ * D_];              // [b][s][e]  V
__device__ __nv_bfloat16 g_Qc[B_ * S_ * D_];              // [b][s][d]  Q/sumsq (masked=0)
__device__ __nv_bfloat16 g_s1part[NSPLIT * B_ * D_ * D_]; // per-split partials (bf16)
__device__ __nv_bfloat16 g_s1c[B_ * D_ * D_];             // [b][d][e]  bf16 (reduced)
__device__ float         g_t[B_ * D_];                    // exact colsum (masked rows)
__device__ unsigned char g_msk[B_ * S_];
__device__ int           g_mask_mode;                     // 0=bool,1=int32,2=float32

// ---------------------------------------------------------------------------
// Helpers
// ---------------------------------------------------------------------------
__device__ __forceinline__ void cp16(void* smem_dst, const void* gsrc) {
    uint32_t a = (uint32_t)__cvta_generic_to_shared(smem_dst);
    asm volatile("cp.async.cg.shared.global [%0], [%1], 16;" :: "r"(a), "l"(gsrc));
}
__device__ __forceinline__ void cp_commit() { asm volatile("cp.async.commit_group;"); }
#define CP_WAIT(N) asm volatile("cp.async.wait_group %0;" :: "n"(N))

__device__ __forceinline__ void ldsmx4(uint32_t* r, uint32_t addr) {
    asm volatile("ldmatrix.sync.aligned.m8n8.x4.shared.b16 {%0,%1,%2,%3}, [%4];"
                 : "=r"(r[0]), "=r"(r[1]), "=r"(r[2]), "=r"(r[3]) : "r"(addr));
}
__device__ __forceinline__ void ldsmx4t(uint32_t* r, uint32_t addr) {
    asm volatile("ldmatrix.sync.aligned.m8n8.x4.trans.shared.b16 {%0,%1,%2,%3}, [%4];"
                 : "=r"(r[0]), "=r"(r[1]), "=r"(r[2]), "=r"(r[3]) : "r"(addr));
}
__device__ __forceinline__ void mma16816(float* d, const uint32_t* a, const uint32_t* b) {
    asm volatile(
        "mma.sync.aligned.m16n8k16.row.col.f32.bf16.bf16.f32 "
        "{%0,%1,%2,%3},{%4,%5,%6,%7},{%8,%9},{%0,%1,%2,%3};"
        : "+f"(d[0]), "+f"(d[1]), "+f"(d[2]), "+f"(d[3])
        : "r"(a[0]), "r"(a[1]), "r"(a[2]), "r"(a[3]), "r"(b[0]), "r"(b[1]));
}

__device__ __forceinline__ uint4 pack8(float4 a, float4 b, float m) {
    __nv_bfloat162 h0 = __floats2bfloat162_rn(a.x * m, a.y * m);
    __nv_bfloat162 h1 = __floats2bfloat162_rn(a.z * m, a.w * m);
    __nv_bfloat162 h2 = __floats2bfloat162_rn(b.x * m, b.y * m);
    __nv_bfloat162 h3 = __floats2bfloat162_rn(b.z * m, b.w * m);
    uint4 o;
    o.x = *reinterpret_cast<uint32_t*>(&h0);
    o.y = *reinterpret_cast<uint32_t*>(&h1);
    o.z = *reinterpret_cast<uint32_t*>(&h2);
    o.w = *reinterpret_cast<uint32_t*>(&h3);
    return o;
}

// ---------------------------------------------------------------------------
// Block 0: zero g_t.  Block 1: mask dtype detect.
// ---------------------------------------------------------------------------
__global__ void zero_detect_kernel(const unsigned int* __restrict__ m) {
    if (blockIdx.x == 0) {
        reinterpret_cast<float4*>(g_t)[threadIdx.x] = make_float4(0.f, 0.f, 0.f, 0.f);
        reinterpret_cast<float4*>(g_t)[threadIdx.x + 256] = make_float4(0.f, 0.f, 0.f, 0.f);
    } else {
        __shared__ int s_big, s_odd;
        if (threadIdx.x == 0) { s_big = 0; s_odd = 0; }
        __syncthreads();
        int big = 0, odd = 0;
        for (int i = threadIdx.x; i < (B_ * S_) / 4; i += blockDim.x) {
            unsigned int w = m[i];
            unsigned int b0 = w & 0xFFu, b1 = (w >> 8) & 0xFFu,
                         b2 = (w >> 16) & 0xFFu, b3 = w >> 24;
            if (b0 > 1u || b1 > 1u || b2 > 1u || b3 > 1u) big = 1;
            if (w != 0u && w != 1u) odd = 1;
        }
        if (big) s_big = 1;
        if (odd) s_odd = 1;
        __syncthreads();
        if (threadIdx.x == 0) g_mask_mode = s_big ? 2 : (s_odd ? 0 : 1);
    }
}

// ---------------------------------------------------------------------------
// Fused prep.  z==0: KV pass (invb, Kc, Vc, exact t accumulation).
//              z==1: Q pass (sumsq, Qc, mask byte).
// grid (S/32, B, 2), 256 threads.
// ---------------------------------------------------------------------------
__global__ __launch_bounds__(256) void prep_kernel(const float* __restrict__ Q,
                                                   const float* __restrict__ K,
                                                   const float* __restrict__ V,
                                                   const void* __restrict__ m) {
    __shared__ float Vsm[32][264];
    __shared__ float csm[32];
    const int b = blockIdx.y, s0 = blockIdx.x * 32;
    const int tid = threadIdx.x, wid = tid >> 5, lane = tid & 31;
    const size_t base = ((size_t)b * S_ + s0) * D_;

    if (blockIdx.z == 0) {
#pragma unroll
        for (int i = 0; i < 4; i++) {
            int r = wid * 4 + i;
            const float4* kr = reinterpret_cast<const float4*>(K + base + (size_t)r * D_) + lane * 2;
            float4 k0 = kr[0], k1 = kr[1];
            float sk = k0.x * k0.x + k0.y * k0.y + k0.z * k0.z + k0.w * k0.w
                     + k1.x * k1.x + k1.y * k1.y + k1.z * k1.z + k1.w * k1.w;
            float rk = k0.x + k0.y + k0.z + k0.w + k1.x + k1.y + k1.z + k1.w;
#pragma unroll
            for (int o = 16; o; o >>= 1) {
                sk += __shfl_xor_sync(0xFFFFFFFFu, sk, o);
                rk += __shfl_xor_sync(0xFFFFFFFFu, rk, o);
            }
            float ib = 1.0f / sk;
            reinterpret_cast<uint4*>(g_Kc)[(base + (size_t)r * D_) / 8 + lane] = pack8(k0, k1, ib);

            const float4* vr = reinterpret_cast<const float4*>(V + base + (size_t)r * D_) + lane * 2;
            float4 v0 = vr[0], v1 = vr[1];
            *reinterpret_cast<float4*>(&Vsm[r][lane * 8])     = v0;
            *reinterpret_cast<float4*>(&Vsm[r][lane * 8 + 4]) = v1;
            reinterpret_cast<uint4*>(g_Vc)[(base + (size_t)r * D_) / 8 + lane] = pack8(v0, v1, 1.0f);
            if (lane == 0) csm[r] = rk * ib;
        }
        __syncthreads();
        float acc = 0.f;
        int e = tid;
#pragma unroll 8
        for (int s = 0; s < 32; s++) acc += csm[s] * Vsm[s][e];
        atomicAdd(&g_t[b * D_ + e], acc);
    } else {
        const int mode = g_mask_mode;
#pragma unroll
        for (int i = 0; i < 4; i++) {
            int r = wid * 4 + i;
            int g = b * S_ + s0 + r;
            const float4* qr = reinterpret_cast<const float4*>(Q + base + (size_t)r * D_) + lane * 2;
            float4 q0 = qr[0], q1 = qr[1];
            float sq = q0.x * q0.x + q0.y * q0.y + q0.z * q0.z + q0.w * q0.w
                     + q1.x * q1.x + q1.y * q1.y + q1.z * q1.z + q1.w * q1.w;
#pragma unroll
            for (int o = 16; o; o >>= 1) sq += __shfl_xor_sync(0xFFFFFFFFu, sq, o);
            bool mk;
            if (mode == 2)      mk = (reinterpret_cast<const float*>(m)[g] != 0.0f);
            else if (mode == 1) mk = (reinterpret_cast<const int*>(m)[g] != 0);
            else                mk = (reinterpret_cast<const unsigned char*>(m)[g] != 0);
            float mul = mk ? 0.0f : 1.0f / sq;
            reinterpret_cast<uint4*>(g_Qc)[(base + (size_t)r * D_) / 8 + lane] = pack8(q0, q1, mul);
            if (lane == 0) g_msk[g] = mk ? 1 : 0;
        }
    }
}

// ---------------------------------------------------------------------------
// GEMM1: CTA tile 256(d) x 128(e).  8 warps (4m x 2n), warp tile 64x64.
// A = Kc[s][d] (trans ldmatrix); B = Vc[s][e].  Partials bf16.
// grid (2 et, NSPLIT, B).  2-stage cp.async, KC=128.
// ---------------------------------------------------------------------------
#define SRA1 264
#define SRB  136
#define A1BUF (KC * SRA1)
#define B1BUF (KC * SRB)
#define STG1  (A1BUF + B1BUF)
#define G1_SMEM (2 * STG1 * (int)sizeof(__nv_bfloat16))   // 204800 B

__global__ __launch_bounds__(256) void gemm1_kernel() {
    extern __shared__ __nv_bfloat16 dsm[];

    const int tid = threadIdx.x, wid = tid >> 5, lane = tid & 31;
    const int b = blockIdx.z;
    const int et = blockIdx.x * 128;
    const int s0 = blockIdx.y * (S_ / NSPLIT);
    const int m0 = (wid >> 1) * 64, n0 = (wid & 1) * 64;
    const __nv_bfloat16* Kb = g_Kc + (size_t)b * S_ * D_;
    const __nv_bfloat16* Vb = g_Vc + (size_t)b * S_ * D_;

    float acc[4][8][4];
#pragma unroll
    for (int i = 0; i < 4; i++)
#pragma unroll
        for (int j = 0; j < 8; j++)
#pragma unroll
            for (int q = 0; q < 4; q++) acc[i][j][q] = 0.f;

    const int r8 = lane & 7, sel = lane >> 3;
    const int atr = (sel >> 1) * 8 + r8, atc = (sel & 1) * 8;
    const int btr = (sel & 1) * 8 + r8, btc = (sel >> 1) * 8;

    auto load = [&](int ch, int st) {
        const int ss = s0 + ch * KC;
        __nv_bfloat16* Ab = dsm + st * STG1;
        __nv_bfloat16* Bb = Ab + A1BUF;
#pragma unroll
        for (int it = 0; it < 16; it++) {
            int ci = tid + it * 256;
            int row = ci >> 5, c16 = ci & 31;
            cp16(Ab + row * SRA1 + c16 * 8, Kb + (size_t)(ss + row) * D_ + c16 * 8);
        }
#pragma unroll
        for (int it = 0; it < 8; it++) {
            int ci = tid + it * 256;
            int row = ci >> 4, c16 = ci & 15;
            cp16(Bb + row * SRB + c16 * 8, Vb + (size_t)(ss + row) * D_ + et + c16 * 8);
        }
    };

    const int NCH = (S_ / NSPLIT) / KC;   // 4
    load(0, 0); cp_commit();
    for (int ch = 0; ch < NCH; ch++) {
        if (ch + 1 < NCH) { load(ch + 1, (ch + 1) & 1); cp_commit(); CP_WAIT(1); }
        else CP_WAIT(0);
        __syncthreads();
        uint32_t Aaddr = (uint32_t)__cvta_generic_to_shared(dsm + (ch & 1) * STG1);
        uint32_t Baddr = Aaddr + A1BUF * 2;
#pragma unroll
        for (int kk = 0; kk < KC / 16; kk++) {
            uint32_t af[4][4], bf[4][4];
#pragma unroll
            for (int mt = 0; mt < 4; mt++)
                ldsmx4(af[mt], Aaddr + ((kk * 16 + atr) * SRA1 + m0 + mt * 16 + atc) * 2);
#pragma unroll
            for (int nt = 0; nt < 4; nt++)
                ldsmx4t(bf[nt], Baddr + ((kk * 16 + btr) * SRB + n0 + nt * 16 + btc) * 2);
#pragma unroll
            for (int mt = 0; mt < 4; mt++)
#pragma unroll
                for (int nt = 0; nt < 4; nt++) {
                    mma16816(acc[mt][nt * 2],     af[mt], &bf[nt][0]);
                    mma16816(acc[mt][nt * 2 + 1], af[mt], &bf[nt][2]);
                }
        }
        __syncthreads();
    }

    __nv_bfloat16* s1p = g_s1part + ((size_t)blockIdx.y * B_ + b) * D_ * D_;
    const int tr = lane >> 2, tc = (lane & 3) * 2;
#pragma unroll
    for (int mt = 0; mt < 4; mt++) {
        int gd0 = m0 + mt * 16 + tr;
#pragma unroll
        for (int nt = 0; nt < 8; nt++) {
            int ge = et + n0 + nt * 8 + tc;
            __nv_bfloat162 lo = __floats2bfloat162_rn(acc[mt][nt][0], acc[mt][nt][1]);
            __nv_bfloat162 hi = __floats2bfloat162_rn(acc[mt][nt][2], acc[mt][nt][3]);
            *reinterpret_cast<uint32_t*>(&s1p[(size_t)gd0 * D_ + ge]) =
                *reinterpret_cast<uint32_t*>(&lo);
            *reinterpret_cast<uint32_t*>(&s1p[(size_t)(gd0 + 8) * D_ + ge]) =
                *reinterpret_cast<uint32_t*>(&hi);
        }
    }
}

// Reduce NSPLIT bf16 partials (fp32 accumulate) -> bf16.  1 uint2 / thread.
__global__ __launch_bounds__(256) void s1conv_kernel() {
    const int i = blockIdx.x * 256 + threadIdx.x;   // uint2 index, B*D*D/4 total
    const int stride = (B_ * D_ * D_) / 4;
    float s0 = 0.f, s1 = 0.f, s2 = 0.f, s3 = 0.f;
#pragma unroll
    for (int sp = 0; sp < NSPLIT; sp++) {
        uint2 p = reinterpret_cast<const uint2*>(g_s1part)[sp * stride + i];
        float2 f0 = __bfloat1622float2(*reinterpret_cast<__nv_bfloat162*>(&p.x));
        float2 f1 = __bfloat1622float2(*reinterpret_cast<__nv_bfloat162*>(&p.y));
        s0 += f0.x; s1 += f0.y; s2 += f1.x; s3 += f1.y;
    }
    __nv_bfloat162 h0 = __floats2bfloat162_rn(s0, s1);
    __nv_bfloat162 h1 = __floats2bfloat162_rn(s2, s3);
    uint2 o;
    o.x = *reinterpret_cast<uint32_t*>(&h0);
    o.y = *reinterpret_cast<uint32_t*>(&h1);
    reinterpret_cast<uint2*>(g_s1c)[i] = o;
}

// ---------------------------------------------------------------------------
// GEMM2: CTA tile 256(s) x 128(e). 8 warps (4m x 2n), warp 64x64.
// A = Qc[s][d], B = s1c[d][e] (trans).  ts loaded from tiny g_t.
// Masked rows -> NEG/256 * ts[e] (exact).  grid (2 et, 16 st, B).
// ---------------------------------------------------------------------------
#define SRA2 136
#define A2BUF (256 * SRA2)
#define B2BUF (KC * SRB)
#define STG2  (A2BUF + B2BUF)
#define G2_SMEM (2 * STG2 * (int)sizeof(__nv_bfloat16))   // 208896 B

__global__ __launch_bounds__(256) void gemm2_kernel(float* __restrict__ out) {
    extern __shared__ __nv_bfloat16 dsm[];
    __shared__ float ts[128];

    const int tid = threadIdx.x, wid = tid >> 5, lane = tid & 31;
    const int b = blockIdx.z;
    const int et = blockIdx.x * 128, st = blockIdx.y * 256;
    const int m0 = (wid >> 1) * 64, n0 = (wid & 1) * 64;
    const __nv_bfloat16* Qb = g_Qc + ((size_t)b * S_ + st) * D_;
    const __nv_bfloat16* Sb = g_s1c + (size_t)b * D_ * D_;

    if (tid < 128) ts[tid] = g_t[b * D_ + et + tid];

    float acc[4][8][4];
#pragma unroll
    for (int i = 0; i < 4; i++)
#pragma unroll
        for (int j = 0; j < 8; j++)
#pragma unroll
            for (int q = 0; q < 4; q++) acc[i][j][q] = 0.f;

    const int r8 = lane & 7, sel = lane >> 3;
    const int anr = lane & 15, anc = (lane >> 4) * 8;
    const int btr = (sel & 1) * 8 + r8, btc = (sel >> 1) * 8;

    auto load = [&](int ch, int st_) {
        __nv_bfloat16* Ab = dsm + st_ * STG2;
        __nv_bfloat16* Bb = Ab + A2BUF;
#pragma unroll
        for (int it = 0; it < 16; it++) {
            int ci = tid + it * 256;
            int row = ci >> 4, c16 = ci & 15;
            cp16(Ab + row * SRA2 + c16 * 8, Qb + (size_t)row * D_ + ch * KC + c16 * 8);
        }
#pragma unroll
        for (int it = 0; it < 8; it++) {
            int ci = tid + it * 256;
            int row = ci >> 4, c16 = ci & 15;
            cp16(Bb + row * SRB + c16 * 8, Sb + (size_t)(ch * KC + row) * D_ + et + c16 * 8);
        }
    };

    const int NCH = D_ / KC;   // 2
    load(0, 0); cp_commit();
    for (int ch = 0; ch < NCH; ch++) {
        if (ch + 1 < NCH) { load(ch + 1, (ch + 1) & 1); cp_commit(); CP_WAIT(1); }
        else CP_WAIT(0);
        __syncthreads();
        uint32_t Aaddr = (uint32_t)__cvta_generic_to_shared(dsm + (ch & 1) * STG2);
        uint32_t Baddr = Aaddr + A2BUF * 2;
#pragma unroll
        for (int kk = 0; kk < KC / 16; kk++) {
            uint32_t af[4][4], bf[4][4];
#pragma unroll
            for (int mt = 0; mt < 4; mt++)
                ldsmx4(af[mt], Aaddr + ((m0 + mt * 16 + anr) * SRA2 + kk * 16 + anc) * 2);
#pragma unroll
            for (int nt = 0; nt < 4; nt++)
                ldsmx4t(bf[nt], Baddr + ((kk * 16 + btr) * SRB + n0 + nt * 16 + btc) * 2);
#pragma unroll
            for (int mt = 0; mt < 4; mt++)
#pragma unroll
                for (int nt = 0; nt < 4; nt++) {
                    mma16816(acc[mt][nt * 2],     af[mt], &bf[nt][0]);
                    mma16816(acc[mt][nt * 2 + 1], af[mt], &bf[nt][2]);
                }
        }
        __syncthreads();
    }

    const float inv_d = 1.0f / 256.0f;
    const float mc = NEGC * inv_d;
    float* ob = out + (size_t)b * S_ * D_;
    const int tr = lane >> 2, tc = (lane & 3) * 2;
#pragma unroll
    for (int mt = 0; mt < 4; mt++) {
        int r0l = m0 + mt * 16 + tr;
        int gs0 = st + r0l, gs1 = gs0 + 8;
        bool mk0 = (g_msk[b * S_ + gs0] != 0);
        bool mk1 = (g_msk[b * S_ + gs1] != 0);
#pragma unroll
        for (int nt = 0; nt < 8; nt++) {
            int gel = n0 + nt * 8 + tc;
            int ge = et + gel;
            float2 v0, v1;
            if (mk0) v0 = make_float2(mc * ts[gel], mc * ts[gel + 1]);
            else     v0 = make_float2(acc[mt][nt][0] * inv_d, acc[mt][nt][1] * inv_d);
            if (mk1) v1 = make_float2(mc * ts[gel], mc * ts[gel + 1]);
            else     v1 = make_float2(acc[mt][nt][2] * inv_d, acc[mt][nt][3] * inv_d);
            *reinterpret_cast<float2*>(&ob[(size_t)gs0 * D_ + ge]) = v0;
            *reinterpret_cast<float2*>(&ob[(size_t)gs1 * D_ + ge]) = v1;
        }
    }
}

// ---------------------------------------------------------------------------
extern "C" void kernel_launch(void* const* d_in, const int* in_sizes, int n_in,
                              void* d_out, int out_size) {
    const float* Q = reinterpret_cast<const float*>(d_in[0]);
    const float* K = reinterpret_cast<const float*>(d_in[1]);
    const float* V = reinterpret_cast<const float*>(d_in[2]);
    const void*  M = d_in[3];
    float* out = reinterpret_cast<float*>(d_out);

    cudaFuncSetAttribute(gemm1_kernel, cudaFuncAttributeMaxDynamicSharedMemorySize, G1_SMEM);
    cudaFuncSetAttribute(gemm2_kernel, cudaFuncAttributeMaxDynamicSharedMemorySize, G2_SMEM);

    zero_detect_kernel<<<2, 256>>>(reinterpret_cast<const unsigned int*>(M));
    {
        dim3 g(S_ / 32, B_, 2);
        prep_kernel<<<g, 256>>>(Q, K, V, M);
    }
    {
        dim3 g(2, NSPLIT, B_);
        gemm1_kernel<<<g, 256, G1_SMEM>>>();
    }
    s1conv_kernel<<<(B_ * D_ * D_) / (4 * 256), 256>>>();
    {
        dim3 g(2, S_ / 256, B_);
        gemm2_kernel<<<g, 256, G2_SMEM>>>(out);
    }
}

// round 15
// speedup vs baseline: 1.2297x; 1.0066x over previous
#include <cuda_runtime.h>
#include <cuda_bf16.h>
#include <cstdint>

#define NEGC -1000000000.0f
#define B_ 8
#define S_ 4096
#define D_ 256
#define KC 128
#define NSPLIT 8

// ---------------------------------------------------------------------------
// Scratch (__device__ globals; no allocation allowed)
// ---------------------------------------------------------------------------
__device__ __nv_bfloat16 g_Kc[B_ * S_ * D_];              // [b][s][d]  K * invb
__device__ __nv_bfloat16 g_Vc[B_ * S_ * D_];              // [b][s][e]  V
__device__ __nv_bfloat16 g_Qc[B_ * S_ * D_];              // [b][s][d]  Q/sumsq (masked=0)
__device__ __nv_bfloat16 g_s1part[NSPLIT * B_ * D_ * D_]; // per-split partials (bf16)
__device__ __nv_bfloat16 g_s1c[B_ * D_ * D_];             // [b][d][e]  bf16 (reduced)
__device__ float         g_t[B_ * D_];                    // exact colsum (masked rows)
__device__ unsigned char g_msk[B_ * S_];
__device__ int           g_mask_mode;                     // 0=bool,1=int32,2=float32

// ---------------------------------------------------------------------------
// Helpers
// ---------------------------------------------------------------------------
__device__ __forceinline__ void cp16(void* smem_dst, const void* gsrc) {
    uint32_t a = (uint32_t)__cvta_generic_to_shared(smem_dst);
    asm volatile("cp.async.cg.shared.global [%0], [%1], 16;" :: "r"(a), "l"(gsrc));
}
__device__ __forceinline__ void cp_commit() { asm volatile("cp.async.commit_group;"); }
#define CP_WAIT(N) asm volatile("cp.async.wait_group %0;" :: "n"(N))

__device__ __forceinline__ void ldsmx4(uint32_t* r, uint32_t addr) {
    asm volatile("ldmatrix.sync.aligned.m8n8.x4.shared.b16 {%0,%1,%2,%3}, [%4];"
                 : "=r"(r[0]), "=r"(r[1]), "=r"(r[2]), "=r"(r[3]) : "r"(addr));
}
__device__ __forceinline__ void ldsmx4t(uint32_t* r, uint32_t addr) {
    asm volatile("ldmatrix.sync.aligned.m8n8.x4.trans.shared.b16 {%0,%1,%2,%3}, [%4];"
                 : "=r"(r[0]), "=r"(r[1]), "=r"(r[2]), "=r"(r[3]) : "r"(addr));
}
__device__ __forceinline__ void mma16816(float* d, const uint32_t* a, const uint32_t* b) {
    asm volatile(
        "mma.sync.aligned.m16n8k16.row.col.f32.bf16.bf16.f32 "
        "{%0,%1,%2,%3},{%4,%5,%6,%7},{%8,%9},{%0,%1,%2,%3};"
        : "+f"(d[0]), "+f"(d[1]), "+f"(d[2]), "+f"(d[3])
        : "r"(a[0]), "r"(a[1]), "r"(a[2]), "r"(a[3]), "r"(b[0]), "r"(b[1]));
}

__device__ __forceinline__ uint4 pack8(float4 a, float4 b, float m) {
    __nv_bfloat162 h0 = __floats2bfloat162_rn(a.x * m, a.y * m);
    __nv_bfloat162 h1 = __floats2bfloat162_rn(a.z * m, a.w * m);
    __nv_bfloat162 h2 = __floats2bfloat162_rn(b.x * m, b.y * m);
    __nv_bfloat162 h3 = __floats2bfloat162_rn(b.z * m, b.w * m);
    uint4 o;
    o.x = *reinterpret_cast<uint32_t*>(&h0);
    o.y = *reinterpret_cast<uint32_t*>(&h1);
    o.z = *reinterpret_cast<uint32_t*>(&h2);
    o.w = *reinterpret_cast<uint32_t*>(&h3);
    return o;
}

// ---------------------------------------------------------------------------
// Block 0: zero g_t.  Block 1: mask dtype detect.
// ---------------------------------------------------------------------------
__global__ void zero_detect_kernel(const unsigned int* __restrict__ m) {
    if (blockIdx.x == 0) {
        reinterpret_cast<float4*>(g_t)[threadIdx.x] = make_float4(0.f, 0.f, 0.f, 0.f);
        reinterpret_cast<float4*>(g_t)[threadIdx.x + 256] = make_float4(0.f, 0.f, 0.f, 0.f);
    } else {
        __shared__ int s_big, s_odd;
        if (threadIdx.x == 0) { s_big = 0; s_odd = 0; }
        __syncthreads();
        int big = 0, odd = 0;
        for (int i = threadIdx.x; i < (B_ * S_) / 4; i += blockDim.x) {
            unsigned int w = m[i];
            unsigned int b0 = w & 0xFFu, b1 = (w >> 8) & 0xFFu,
                         b2 = (w >> 16) & 0xFFu, b3 = w >> 24;
            if (b0 > 1u || b1 > 1u || b2 > 1u || b3 > 1u) big = 1;
            if (w != 0u && w != 1u) odd = 1;
        }
        if (big) s_big = 1;
        if (odd) s_odd = 1;
        __syncthreads();
        if (threadIdx.x == 0) g_mask_mode = s_big ? 2 : (s_odd ? 0 : 1);
    }
}

// ---------------------------------------------------------------------------
// Fused prep.  z==0: KV pass (invb, Kc, Vc, exact t accumulation).
//              z==1: Q pass (sumsq, Qc, mask byte).
// grid (S/32, B, 2), 256 threads.
// ---------------------------------------------------------------------------
__global__ __launch_bounds__(256) void prep_kernel(const float* __restrict__ Q,
                                                   const float* __restrict__ K,
                                                   const float* __restrict__ V,
                                                   const void* __restrict__ m) {
    __shared__ float Vsm[32][264];
    __shared__ float csm[32];
    const int b = blockIdx.y, s0 = blockIdx.x * 32;
    const int tid = threadIdx.x, wid = tid >> 5, lane = tid & 31;
    const size_t base = ((size_t)b * S_ + s0) * D_;

    if (blockIdx.z == 0) {
#pragma unroll
        for (int i = 0; i < 4; i++) {
            int r = wid * 4 + i;
            const float4* kr = reinterpret_cast<const float4*>(K + base + (size_t)r * D_) + lane * 2;
            float4 k0 = kr[0], k1 = kr[1];
            float sk = k0.x * k0.x + k0.y * k0.y + k0.z * k0.z + k0.w * k0.w
                     + k1.x * k1.x + k1.y * k1.y + k1.z * k1.z + k1.w * k1.w;
            float rk = k0.x + k0.y + k0.z + k0.w + k1.x + k1.y + k1.z + k1.w;
#pragma unroll
            for (int o = 16; o; o >>= 1) {
                sk += __shfl_xor_sync(0xFFFFFFFFu, sk, o);
                rk += __shfl_xor_sync(0xFFFFFFFFu, rk, o);
            }
            float ib = 1.0f / sk;
            reinterpret_cast<uint4*>(g_Kc)[(base + (size_t)r * D_) / 8 + lane] = pack8(k0, k1, ib);

            const float4* vr = reinterpret_cast<const float4*>(V + base + (size_t)r * D_) + lane * 2;
            float4 v0 = vr[0], v1 = vr[1];
            *reinterpret_cast<float4*>(&Vsm[r][lane * 8])     = v0;
            *reinterpret_cast<float4*>(&Vsm[r][lane * 8 + 4]) = v1;
            reinterpret_cast<uint4*>(g_Vc)[(base + (size_t)r * D_) / 8 + lane] = pack8(v0, v1, 1.0f);
            if (lane == 0) csm[r] = rk * ib;
        }
        __syncthreads();
        float acc = 0.f;
        int e = tid;
#pragma unroll 8
        for (int s = 0; s < 32; s++) acc += csm[s] * Vsm[s][e];
        atomicAdd(&g_t[b * D_ + e], acc);
    } else {
        const int mode = g_mask_mode;
#pragma unroll
        for (int i = 0; i < 4; i++) {
            int r = wid * 4 + i;
            int g = b * S_ + s0 + r;
            const float4* qr = reinterpret_cast<const float4*>(Q + base + (size_t)r * D_) + lane * 2;
            float4 q0 = qr[0], q1 = qr[1];
            float sq = q0.x * q0.x + q0.y * q0.y + q0.z * q0.z + q0.w * q0.w
                     + q1.x * q1.x + q1.y * q1.y + q1.z * q1.z + q1.w * q1.w;
#pragma unroll
            for (int o = 16; o; o >>= 1) sq += __shfl_xor_sync(0xFFFFFFFFu, sq, o);
            bool mk;
            if (mode == 2)      mk = (reinterpret_cast<const float*>(m)[g] != 0.0f);
            else if (mode == 1) mk = (reinterpret_cast<const int*>(m)[g] != 0);
            else                mk = (reinterpret_cast<const unsigned char*>(m)[g] != 0);
            float mul = mk ? 0.0f : 1.0f / sq;
            reinterpret_cast<uint4*>(g_Qc)[(base + (size_t)r * D_) / 8 + lane] = pack8(q0, q1, mul);
            if (lane == 0) g_msk[g] = mk ? 1 : 0;
        }
    }
}

// ---------------------------------------------------------------------------
// GEMM1: CTA tile 256(d) x 128(e).  8 warps (4m x 2n), warp tile 64x64.
// A = Kc[s][d] (trans ldmatrix); B = Vc[s][e].  Partials bf16.
// grid (2 et, NSPLIT, B).  2-stage cp.async, KC=128.
// ---------------------------------------------------------------------------
#define SRA1 264
#define SRB  136
#define A1BUF (KC * SRA1)
#define B1BUF (KC * SRB)
#define STG1  (A1BUF + B1BUF)
#define G1_SMEM (2 * STG1 * (int)sizeof(__nv_bfloat16))   // 204800 B

__global__ __launch_bounds__(256) void gemm1_kernel() {
    extern __shared__ __nv_bfloat16 dsm[];

    const int tid = threadIdx.x, wid = tid >> 5, lane = tid & 31;
    const int b = blockIdx.z;
    const int et = blockIdx.x * 128;
    const int s0 = blockIdx.y * (S_ / NSPLIT);
    const int m0 = (wid >> 1) * 64, n0 = (wid & 1) * 64;
    const __nv_bfloat16* Kb = g_Kc + (size_t)b * S_ * D_;
    const __nv_bfloat16* Vb = g_Vc + (size_t)b * S_ * D_;

    float acc[4][8][4];
#pragma unroll
    for (int i = 0; i < 4; i++)
#pragma unroll
        for (int j = 0; j < 8; j++)
#pragma unroll
            for (int q = 0; q < 4; q++) acc[i][j][q] = 0.f;

    const int r8 = lane & 7, sel = lane >> 3;
    const int atr = (sel >> 1) * 8 + r8, atc = (sel & 1) * 8;
    const int btr = (sel & 1) * 8 + r8, btc = (sel >> 1) * 8;

    auto load = [&](int ch, int st) {
        const int ss = s0 + ch * KC;
        __nv_bfloat16* Ab = dsm + st * STG1;
        __nv_bfloat16* Bb = Ab + A1BUF;
#pragma unroll
        for (int it = 0; it < 16; it++) {
            int ci = tid + it * 256;
            int row = ci >> 5, c16 = ci & 31;
            cp16(Ab + row * SRA1 + c16 * 8, Kb + (size_t)(ss + row) * D_ + c16 * 8);
        }
#pragma unroll
        for (int it = 0; it < 8; it++) {
            int ci = tid + it * 256;
            int row = ci >> 4, c16 = ci & 15;
            cp16(Bb + row * SRB + c16 * 8, Vb + (size_t)(ss + row) * D_ + et + c16 * 8);
        }
    };

    const int NCH = (S_ / NSPLIT) / KC;   // 4
    load(0, 0); cp_commit();
    for (int ch = 0; ch < NCH; ch++) {
        if (ch + 1 < NCH) { load(ch + 1, (ch + 1) & 1); cp_commit(); CP_WAIT(1); }
        else CP_WAIT(0);
        __syncthreads();
        uint32_t Aaddr = (uint32_t)__cvta_generic_to_shared(dsm + (ch & 1) * STG1);
        uint32_t Baddr = Aaddr + A1BUF * 2;
#pragma unroll
        for (int kk = 0; kk < KC / 16; kk++) {
            uint32_t af[4][4], bf[4][4];
#pragma unroll
            for (int mt = 0; mt < 4; mt++)
                ldsmx4(af[mt], Aaddr + ((kk * 16 + atr) * SRA1 + m0 + mt * 16 + atc) * 2);
#pragma unroll
            for (int nt = 0; nt < 4; nt++)
                ldsmx4t(bf[nt], Baddr + ((kk * 16 + btr) * SRB + n0 + nt * 16 + btc) * 2);
#pragma unroll
            for (int mt = 0; mt < 4; mt++)
#pragma unroll
                for (int nt = 0; nt < 4; nt++) {
                    mma16816(acc[mt][nt * 2],     af[mt], &bf[nt][0]);
                    mma16816(acc[mt][nt * 2 + 1], af[mt], &bf[nt][2]);
                }
        }
        __syncthreads();
    }

    __nv_bfloat16* s1p = g_s1part + ((size_t)blockIdx.y * B_ + b) * D_ * D_;
    const int tr = lane >> 2, tc = (lane & 3) * 2;
#pragma unroll
    for (int mt = 0; mt < 4; mt++) {
        int gd0 = m0 + mt * 16 + tr;
#pragma unroll
        for (int nt = 0; nt < 8; nt++) {
            int ge = et + n0 + nt * 8 + tc;
            __nv_bfloat162 lo = __floats2bfloat162_rn(acc[mt][nt][0], acc[mt][nt][1]);
            __nv_bfloat162 hi = __floats2bfloat162_rn(acc[mt][nt][2], acc[mt][nt][3]);
            *reinterpret_cast<uint32_t*>(&s1p[(size_t)gd0 * D_ + ge]) =
                *reinterpret_cast<uint32_t*>(&lo);
            *reinterpret_cast<uint32_t*>(&s1p[(size_t)(gd0 + 8) * D_ + ge]) =
                *reinterpret_cast<uint32_t*>(&hi);
        }
    }
}

// Reduce NSPLIT bf16 partials (fp32 accumulate) -> bf16.  1 uint2 / thread.
__global__ __launch_bounds__(256) void s1conv_kernel() {
    const int i = blockIdx.x * 256 + threadIdx.x;   // uint2 index, B*D*D/4 total
    const int stride = (B_ * D_ * D_) / 4;
    float s0 = 0.f, s1 = 0.f, s2 = 0.f, s3 = 0.f;
#pragma unroll
    for (int sp = 0; sp < NSPLIT; sp++) {
        uint2 p = reinterpret_cast<const uint2*>(g_s1part)[sp * stride + i];
        float2 f0 = __bfloat1622float2(*reinterpret_cast<__nv_bfloat162*>(&p.x));
        float2 f1 = __bfloat1622float2(*reinterpret_cast<__nv_bfloat162*>(&p.y));
        s0 += f0.x; s1 += f0.y; s2 += f1.x; s3 += f1.y;
    }
    __nv_bfloat162 h0 = __floats2bfloat162_rn(s0, s1);
    __nv_bfloat162 h1 = __floats2bfloat162_rn(s2, s3);
    uint2 o;
    o.x = *reinterpret_cast<uint32_t*>(&h0);
    o.y = *reinterpret_cast<uint32_t*>(&h1);
    reinterpret_cast<uint2*>(g_s1c)[i] = o;
}

// ---------------------------------------------------------------------------
// GEMM2: CTA tile 256(s) x 128(e). 8 warps (4m x 2n), warp 64x64.
// A = Qc[s][d], B = s1c[d][e] (trans).  ts loaded from tiny g_t.
// Epilogue staged through smem for fully coalesced 128B output stores.
// grid (2 et, 16 st, B).
// ---------------------------------------------------------------------------
#define SRA2 136
#define A2BUF (256 * SRA2)
#define B2BUF (KC * SRB)
#define STG2  (A2BUF + B2BUF)
#define G2_SMEM (2 * STG2 * (int)sizeof(__nv_bfloat16))   // 208896 B
#define OSR 132   // epilogue stage row stride (floats)

__global__ __launch_bounds__(256) void gemm2_kernel(float* __restrict__ out) {
    extern __shared__ __nv_bfloat16 dsm[];
    __shared__ float ts[128];
    __shared__ unsigned char msks[256];

    const int tid = threadIdx.x, wid = tid >> 5, lane = tid & 31;
    const int b = blockIdx.z;
    const int et = blockIdx.x * 128, st = blockIdx.y * 256;
    const int m0 = (wid >> 1) * 64, n0 = (wid & 1) * 64;
    const __nv_bfloat16* Qb = g_Qc + ((size_t)b * S_ + st) * D_;
    const __nv_bfloat16* Sb = g_s1c + (size_t)b * D_ * D_;

    if (tid < 128) ts[tid] = g_t[b * D_ + et + tid];
    msks[tid] = g_msk[b * S_ + st + tid];

    float acc[4][8][4];
#pragma unroll
    for (int i = 0; i < 4; i++)
#pragma unroll
        for (int j = 0; j < 8; j++)
#pragma unroll
            for (int q = 0; q < 4; q++) acc[i][j][q] = 0.f;

    const int r8 = lane & 7, sel = lane >> 3;
    const int anr = lane & 15, anc = (lane >> 4) * 8;
    const int btr = (sel & 1) * 8 + r8, btc = (sel >> 1) * 8;

    auto load = [&](int ch, int st_) {
        __nv_bfloat16* Ab = dsm + st_ * STG2;
        __nv_bfloat16* Bb = Ab + A2BUF;
#pragma unroll
        for (int it = 0; it < 16; it++) {
            int ci = tid + it * 256;
            int row = ci >> 4, c16 = ci & 15;
            cp16(Ab + row * SRA2 + c16 * 8, Qb + (size_t)row * D_ + ch * KC + c16 * 8);
        }
#pragma unroll
        for (int it = 0; it < 8; it++) {
            int ci = tid + it * 256;
            int row = ci >> 4, c16 = ci & 15;
            cp16(Bb + row * SRB + c16 * 8, Sb + (size_t)(ch * KC + row) * D_ + et + c16 * 8);
        }
    };

    const int NCH = D_ / KC;   // 2
    load(0, 0); cp_commit();
    for (int ch = 0; ch < NCH; ch++) {
        if (ch + 1 < NCH) { load(ch + 1, (ch + 1) & 1); cp_commit(); CP_WAIT(1); }
        else CP_WAIT(0);
        __syncthreads();
        uint32_t Aaddr = (uint32_t)__cvta_generic_to_shared(dsm + (ch & 1) * STG2);
        uint32_t Baddr = Aaddr + A2BUF * 2;
#pragma unroll
        for (int kk = 0; kk < KC / 16; kk++) {
            uint32_t af[4][4], bf[4][4];
#pragma unroll
            for (int mt = 0; mt < 4; mt++)
                ldsmx4(af[mt], Aaddr + ((m0 + mt * 16 + anr) * SRA2 + kk * 16 + anc) * 2);
#pragma unroll
            for (int nt = 0; nt < 4; nt++)
                ldsmx4t(bf[nt], Baddr + ((kk * 16 + btr) * SRB + n0 + nt * 16 + btc) * 2);
#pragma unroll
            for (int mt = 0; mt < 4; mt++)
#pragma unroll
                for (int nt = 0; nt < 4; nt++) {
                    mma16816(acc[mt][nt * 2],     af[mt], &bf[nt][0]);
                    mma16816(acc[mt][nt * 2 + 1], af[mt], &bf[nt][2]);
                }
        }
        __syncthreads();
    }

    // ---- Epilogue: stage accumulators in (dead) pipeline smem, then write
    // fully coalesced rows.  Stage: fp32 [256][OSR] = 135 KB <= 204 KB dsm.
    float* stg = reinterpret_cast<float*>(dsm);
    const int tr = lane >> 2, tc = (lane & 3) * 2;
#pragma unroll
    for (int mt = 0; mt < 4; mt++) {
        int r0l = m0 + mt * 16 + tr;
#pragma unroll
        for (int nt = 0; nt < 8; nt++) {
            int col = n0 + nt * 8 + tc;
            *reinterpret_cast<float2*>(&stg[r0l * OSR + col]) =
                make_float2(acc[mt][nt][0], acc[mt][nt][1]);
            *reinterpret_cast<float2*>(&stg[(r0l + 8) * OSR + col]) =
                make_float2(acc[mt][nt][2], acc[mt][nt][3]);
        }
    }
    __syncthreads();

    const float inv_d = 1.0f / 256.0f;
    const float mc = NEGC * inv_d;
    float* ob = out + (size_t)b * S_ * D_;
    // 256 rows x 32 float4-cols; each iteration a warp covers one full row.
#pragma unroll
    for (int it = 0; it < 32; it++) {
        int idx = tid + it * 256;
        int row = idx >> 5;            // 0..255
        int c4 = (idx & 31) * 4;       // 0..124
        float4 v;
        if (msks[row]) {
            v = make_float4(mc * ts[c4], mc * ts[c4 + 1], mc * ts[c4 + 2], mc * ts[c4 + 3]);
        } else {
            v = *reinterpret_cast<float4*>(&stg[row * OSR + c4]);
            v.x *= inv_d; v.y *= inv_d; v.z *= inv_d; v.w *= inv_d;
        }
        *reinterpret_cast<float4*>(&ob[(size_t)(st + row) * D_ + et + c4]) = v;
    }
}

// ---------------------------------------------------------------------------
extern "C" void kernel_launch(void* const* d_in, const int* in_sizes, int n_in,
                              void* d_out, int out_size) {
    const float* Q = reinterpret_cast<const float*>(d_in[0]);
    const float* K = reinterpret_cast<const float*>(d_in[1]);
    const float* V = reinterpret_cast<const float*>(d_in[2]);
    const void*  M = d_in[3];
    float* out = reinterpret_cast<float*>(d_out);

    cudaFuncSetAttribute(gemm1_kernel, cudaFuncAttributeMaxDynamicSharedMemorySize, G1_SMEM);
    cudaFuncSetAttribute(gemm2_kernel, cudaFuncAttributeMaxDynamicSharedMemorySize, G2_SMEM);

    zero_detect_kernel<<<2, 256>>>(reinterpret_cast<const unsigned int*>(M));
    {
        dim3 g(S_ / 32, B_, 2);
        prep_kernel<<<g, 256>>>(Q, K, V, M);
    }
    {
        dim3 g(2, NSPLIT, B_);
        gemm1_kernel<<<g, 256, G1_SMEM>>>();
    }
    s1conv_kernel<<<(B_ * D_ * D_) / (4 * 256), 256>>>();
    {
        dim3 g(2, S_ / 256, B_);
        gemm2_kernel<<<g, 256, G2_SMEM>>>(out);
    }
}